// round 6
// baseline (speedup 1.0000x reference)
#include <cuda_runtime.h>
#include <cuda_bf16.h>
#include <math.h>
#include <stdint.h>

// Problem constants
#define B_  2
#define L_  2048
#define D_  1024
#define H_  16
#define HD  64
#define M_  (B_ * L_)   // 4096

// ---------------------------------------------------------------------------
// Scratch (static device globals; no dynamic allocation allowed)
// All activation tensors live as pre-split bf16 hi/lo pairs.
// ---------------------------------------------------------------------------
__device__ __nv_bfloat16 g_xh[M_ * D_];      // split of x; reused for y
__device__ __nv_bfloat16 g_xl[M_ * D_];
__device__ __nv_bfloat16 g_qh[M_ * D_];
__device__ __nv_bfloat16 g_ql[M_ * D_];
__device__ __nv_bfloat16 g_kh[M_ * D_];
__device__ __nv_bfloat16 g_kl[M_ * D_];
__device__ __nv_bfloat16 g_vh[M_ * D_];
__device__ __nv_bfloat16 g_vl[M_ * D_];
__device__ __nv_bfloat16 g_wh[4 * D_ * D_];  // transposed split weights
__device__ __nv_bfloat16 g_wl[4 * D_ * D_];
__device__ float2 g_rt[L_ * 32];             // (sin, cos) per (pos, pair)

// ---------------------------------------------------------------------------
// Helpers
// ---------------------------------------------------------------------------
__device__ __forceinline__ void mma16816(float* c,
                                         uint32_t a0, uint32_t a1,
                                         uint32_t a2, uint32_t a3,
                                         uint32_t b0, uint32_t b1)
{
    asm volatile(
        "mma.sync.aligned.m16n8k16.row.col.f32.bf16.bf16.f32 "
        "{%0,%1,%2,%3}, {%4,%5,%6,%7}, {%8,%9}, {%0,%1,%2,%3};"
        : "+f"(c[0]), "+f"(c[1]), "+f"(c[2]), "+f"(c[3])
        : "r"(a0), "r"(a1), "r"(a2), "r"(a3), "r"(b0), "r"(b1));
}

__device__ __forceinline__ void split2(float x0, float x1,
                                       uint32_t& hi, uint32_t& lo)
{
    __nv_bfloat162 hp = __floats2bfloat162_rn(x0, x1);
    float2 hf = __bfloat1622float2(hp);
    __nv_bfloat162 lp = __floats2bfloat162_rn(x0 - hf.x, x1 - hf.y);
    hi = *(uint32_t*)&hp;
    lo = *(uint32_t*)&lp;
}

__device__ __forceinline__ uint32_t smem_u32(const void* p) {
    uint32_t a;
    asm("{ .reg .u64 t; cvta.to.shared.u64 t, %1; cvt.u32.u64 %0, t; }"
        : "=r"(a) : "l"(p));
    return a;
}

__device__ __forceinline__ void cpa16(uint32_t dst, const void* src) {
    asm volatile("cp.async.cg.shared.global [%0], [%1], 16;"
                 :: "r"(dst), "l"(src));
}
#define CP_COMMIT  asm volatile("cp.async.commit_group;")
#define CP_WAIT(n) asm volatile("cp.async.wait_group %0;" :: "n"(n))

// ---------------------------------------------------------------------------
// RoPE table: g_rt[pos*32 + i] = (sin, cos)(pos * 10000^(-2i/64))
// ---------------------------------------------------------------------------
__global__ __launch_bounds__(256) void ropetab_kernel()
{
    int idx = blockIdx.x * blockDim.x + threadIdx.x;   // < 65536
    int pos = idx >> 5;
    int i   = idx & 31;
    float freq = exp2f(-13.287712379549449f * (float)(2 * i) * (1.0f / 64.0f));
    float s, c;
    sincosf((float)pos * freq, &s, &c);
    g_rt[idx] = make_float2(s, c);
}

// ---------------------------------------------------------------------------
// split_f32: elementwise split of an f32 array into bf16 hi/lo
// ---------------------------------------------------------------------------
__global__ __launch_bounds__(256) void split_f32(
    const float* __restrict__ src,
    __nv_bfloat16* __restrict__ hi, __nv_bfloat16* __restrict__ lo)
{
    int i = blockIdx.x * blockDim.x + threadIdx.x;   // float4 index
    float4 v = ((const float4*)src)[i];
    uint32_t h0, l0, h1, l1;
    split2(v.x, v.y, h0, l0);
    split2(v.z, v.w, h1, l1);
    ((uint32_t*)hi)[2 * i]     = h0;
    ((uint32_t*)hi)[2 * i + 1] = h1;
    ((uint32_t*)lo)[2 * i]     = l0;
    ((uint32_t*)lo)[2 * i + 1] = l1;
}

// ---------------------------------------------------------------------------
// splitw: transpose + split weights
// ---------------------------------------------------------------------------
__global__ __launch_bounds__(256) void splitw(
    const float* __restrict__ W0, const float* __restrict__ W1,
    const float* __restrict__ W2, const float* __restrict__ W3)
{
    __shared__ float tile[32][33];
    const float* srcs[4] = {W0, W1, W2, W3};
    const float* src = srcs[blockIdx.z];

    int x = blockIdx.x * 32 + threadIdx.x;   // n
    int y = blockIdx.y * 32 + threadIdx.y;   // k
#pragma unroll
    for (int i = 0; i < 4; ++i)
        tile[threadIdx.y + i * 8][threadIdx.x] = src[(size_t)(y + i * 8) * D_ + x];
    __syncthreads();

    uint32_t* whu = (uint32_t*)g_wh;
    uint32_t* wlu = (uint32_t*)g_wl;
    int tid2 = threadIdx.y * 32 + threadIdx.x;
#pragma unroll
    for (int p = 0; p < 2; ++p) {
        int q = tid2 + p * 256;
        int nl = q >> 4;
        int kp = q & 15;
        uint32_t hi, lo;
        split2(tile[2 * kp][nl], tile[2 * kp + 1][nl], hi, lo);
        size_t o = ((size_t)(blockIdx.z * D_ + blockIdx.x * 32 + nl) * D_
                    + blockIdx.y * 32) / 2 + kp;
        whu[o] = hi;
        wlu[o] = lo;
    }
}

// ---------------------------------------------------------------------------
// gemm_qkv: C = alpha * A @ B^T, pre-split bf16 operands, cp.async 2-stage.
// mode 0: fused QKV — epilogue applies RoPE (Q,K via table) and writes
//         split bf16 hi/lo into (Qh,Ql)/(Kh,Kl)/(Vh,Vl).
// mode 1: plain f32 output to Of32.
// ---------------------------------------------------------------------------
#define PST 20                       // smem row stride in u32 (80 bytes)
#define TILE_B (128 * PST * 4)       // 10240 bytes per operand tile
#define STAGE_B (4 * TILE_B)         // 40960
#define GEMM2_SMEM (2 * STAGE_B)     // 81920

__global__ __launch_bounds__(256, 2) void gemm_qkv(
    const __nv_bfloat16* __restrict__ Agh, const __nv_bfloat16* __restrict__ Agl,
    const __nv_bfloat16* __restrict__ Bgh, const __nv_bfloat16* __restrict__ Bgl,
    uint32_t* __restrict__ Qh, uint32_t* __restrict__ Ql,
    uint32_t* __restrict__ Kh, uint32_t* __restrict__ Kl,
    uint32_t* __restrict__ Vh, uint32_t* __restrict__ Vl,
    float* __restrict__ Of32, float alpha0, int mode)
{
    extern __shared__ char smp[];
    const uint32_t sb = smem_u32(smp);

    const int tid = threadIdx.x;
    const int wid = tid >> 5;
    const int lane = tid & 31;
    const int wm = wid & 1;
    const int wn = wid >> 1;
    const int g  = lane >> 2;
    const int t  = lane & 3;
    const int m0 = blockIdx.y * 128;
    const int nb = blockIdx.x;
    const int nrow0 = nb * 128;
    const int sel = nb >> 3;
    const float alpha = (sel == 0) ? alpha0 : 1.0f;
    const int n0 = (nb & 7) * 128;

    float acc[4][4][4];
#pragma unroll
    for (int i = 0; i < 4; ++i)
#pragma unroll
        for (int j = 0; j < 4; ++j)
#pragma unroll
            for (int r = 0; r < 4; ++r) acc[i][j][r] = 0.0f;

    const int ldrow = tid >> 2;          // 0..63
    const int ldcc  = tid & 3;

    auto issue = [&](int c, int s) {
        const int k0 = c * 32;
#pragma unroll
        for (int i = 0; i < 2; ++i) {
            int row = ldrow + i * 64;
            uint32_t so = (uint32_t)(s * STAGE_B + row * 80 + ldcc * 16);
            size_t ga = (size_t)(m0 + row) * D_ + k0 + ldcc * 8;
            size_t gb = (size_t)(nrow0 + row) * D_ + k0 + ldcc * 8;
            cpa16(sb + so,              Agh + ga);
            cpa16(sb + so + TILE_B,     Agl + ga);
            cpa16(sb + so + 2 * TILE_B, Bgh + gb);
            cpa16(sb + so + 3 * TILE_B, Bgl + gb);
        }
    };

    issue(0, 0);
    CP_COMMIT;

    for (int c = 0; c < D_ / 32; ++c) {
        const int s = c & 1;
        if (c + 1 < D_ / 32) {
            issue(c + 1, s ^ 1);
            CP_COMMIT;
            CP_WAIT(1);
        } else {
            CP_WAIT(0);
        }
        __syncthreads();

        const uint32_t* Ah = (const uint32_t*)(smp + s * STAGE_B);
        const uint32_t* Al = (const uint32_t*)(smp + s * STAGE_B + TILE_B);
        const uint32_t* Bh = (const uint32_t*)(smp + s * STAGE_B + 2 * TILE_B);
        const uint32_t* Bl = (const uint32_t*)(smp + s * STAGE_B + 3 * TILE_B);

#pragma unroll
        for (int ks = 0; ks < 2; ++ks) {
            const int pc = ks * 8 + t;
            uint32_t bh[4][2], bl[4][2];
#pragma unroll
            for (int j = 0; j < 4; ++j) {
                int nr = wn * 32 + j * 8 + g;
                bh[j][0] = Bh[nr * PST + pc];
                bh[j][1] = Bh[nr * PST + pc + 4];
                bl[j][0] = Bl[nr * PST + pc];
                bl[j][1] = Bl[nr * PST + pc + 4];
            }
#pragma unroll
            for (int i = 0; i < 4; ++i) {
                int mr = wm * 64 + i * 16 + g;
                uint32_t ah0 = Ah[mr * PST + pc];
                uint32_t ah1 = Ah[(mr + 8) * PST + pc];
                uint32_t ah2 = Ah[mr * PST + pc + 4];
                uint32_t ah3 = Ah[(mr + 8) * PST + pc + 4];
                uint32_t al0 = Al[mr * PST + pc];
                uint32_t al1 = Al[(mr + 8) * PST + pc];
                uint32_t al2 = Al[mr * PST + pc + 4];
                uint32_t al3 = Al[(mr + 8) * PST + pc + 4];
#pragma unroll
                for (int j = 0; j < 4; ++j) {
                    mma16816(acc[i][j], ah0, ah1, ah2, ah3, bh[j][0], bh[j][1]);
                    mma16816(acc[i][j], al0, al1, al2, al3, bh[j][0], bh[j][1]);
                    mma16816(acc[i][j], ah0, ah1, ah2, ah3, bl[j][0], bl[j][1]);
                }
            }
        }
        __syncthreads();
    }

    // ---- Epilogue
    uint32_t* Uh = (sel == 0) ? Qh : (sel == 1) ? Kh : Vh;
    uint32_t* Ul = (sel == 0) ? Ql : (sel == 1) ? Kl : Vl;

#pragma unroll
    for (int i = 0; i < 4; ++i) {
        int row = m0 + wm * 64 + i * 16 + g;
#pragma unroll
        for (int j = 0; j < 4; ++j) {
            int col = n0 + wn * 32 + j * 8 + t * 2;
            float2 o0 = make_float2(alpha * acc[i][j][0], alpha * acc[i][j][1]);
            float2 o1 = make_float2(alpha * acc[i][j][2], alpha * acc[i][j][3]);
            if (mode == 1) {
                *(float2*)(Of32 + (size_t)row * D_ + col)       = o0;
                *(float2*)(Of32 + (size_t)(row + 8) * D_ + col) = o1;
            } else {
                if (sel < 2) {   // RoPE for Q and K
                    int ii = (col >> 1) & 31;
                    float2 sc0 = g_rt[(row & (L_ - 1)) * 32 + ii];
                    float2 sc1 = g_rt[((row + 8) & (L_ - 1)) * 32 + ii];
                    o0 = make_float2(o0.x * sc0.y - o0.y * sc0.x,
                                     o0.y * sc0.y + o0.x * sc0.x);
                    o1 = make_float2(o1.x * sc1.y - o1.y * sc1.x,
                                     o1.y * sc1.y + o1.x * sc1.x);
                }
                uint32_t h0, l0, h1, l1;
                split2(o0.x, o0.y, h0, l0);
                split2(o1.x, o1.y, h1, l1);
                size_t u0 = ((size_t)row * D_ + col) >> 1;
                size_t u1 = ((size_t)(row + 8) * D_ + col) >> 1;
                Uh[u0] = h0; Ul[u0] = l0;
                Uh[u1] = h1; Ul[u1] = l1;
            }
        }
    }
}

// ---------------------------------------------------------------------------
// flash2: tensor-core flash attention on pre-split inputs.
// Q frags: direct u32 loads. K tiles: cp.async raw copy. V: LDG.64 + PRMT
// transpose. Output written pre-split (bf16 hi/lo) for the Wo GEMM.
// ---------------------------------------------------------------------------
#define FST 36

__global__ __launch_bounds__(256, 2) void flash2(
    const uint32_t* __restrict__ qh, const uint32_t* __restrict__ ql,
    const uint32_t* __restrict__ kh, const uint32_t* __restrict__ kl,
    const uint32_t* __restrict__ vh, const uint32_t* __restrict__ vl,
    uint32_t* __restrict__ yh, uint32_t* __restrict__ yl)
{
    __shared__ uint32_t Khi[64 * FST], Klo[64 * FST];
    __shared__ uint32_t Vhi[64 * FST], Vlo[64 * FST];

    const int tid  = threadIdx.x;
    const int wid  = tid >> 5;
    const int lane = tid & 31;
    const int g = lane >> 2;
    const int t = lane & 3;
    const int q0 = blockIdx.x * 128;
    const int h  = blockIdx.y;
    const int b  = blockIdx.z;

    const uint32_t kbh = smem_u32(Khi);
    const uint32_t kbl = smem_u32(Klo);

    // ---- Q fragments (direct loads from pre-split buffers)
    uint32_t qhf[4][4], qlf[4][4];
    {
        int r0 = b * L_ + q0 + wid * 16 + g;
        const uint32_t* p  = qh + (size_t)r0 * 512 + h * 32;
        const uint32_t* pl = ql + (size_t)r0 * 512 + h * 32;
#pragma unroll
        for (int ks = 0; ks < 4; ++ks) {
            qhf[ks][0] = p[ks * 8 + t];
            qhf[ks][1] = p[8 * 512 + ks * 8 + t];
            qhf[ks][2] = p[ks * 8 + t + 4];
            qhf[ks][3] = p[8 * 512 + ks * 8 + t + 4];
            qlf[ks][0] = pl[ks * 8 + t];
            qlf[ks][1] = pl[8 * 512 + ks * 8 + t];
            qlf[ks][2] = pl[ks * 8 + t + 4];
            qlf[ks][3] = pl[8 * 512 + ks * 8 + t + 4];
        }
    }

    float acc[8][4];
#pragma unroll
    for (int j = 0; j < 8; ++j)
#pragma unroll
        for (int r = 0; r < 4; ++r) acc[j][r] = 0.0f;
    float m0r = -1e30f, m1r = -1e30f, l0r = 0.0f, l1r = 0.0f;

    for (int tile = 0; tile < L_ / 64; ++tile) {
        __syncthreads();   // previous tile fully consumed

        // ---- K tile via cp.async (raw copies; layout matches fragments)
        {
            int row = tid >> 2;                 // 0..63
            int ch  = tid & 3;                  // chunks ch, ch+4
            size_t uoff = (size_t)(b * L_ + tile * 64 + row) * 512 + h * 32;
            uint32_t so = (uint32_t)(row * (FST * 4));
            cpa16(kbh + so + ch * 16,       kh + uoff + ch * 4);
            cpa16(kbh + so + (ch + 4) * 16, kh + uoff + (ch + 4) * 4);
            cpa16(kbl + so + ch * 16,       kl + uoff + ch * 4);
            cpa16(kbl + so + (ch + 4) * 16, kl + uoff + (ch + 4) * 4);
        }
        CP_COMMIT;

        // ---- V tile transposed via LDG.64 + PRMT
#pragma unroll
        for (int it = 0; it < 2; ++it) {
            int idx = tid + it * 256;           // 0..511
            int kp  = idx & 31;                 // key pair
            int dpp = idx >> 5;                 // 0..15 -> d = 4*dpp..
            size_t g0 = (size_t)(b * L_ + tile * 64 + 2 * kp) * 512 + h * 32 + 2 * dpp;
            size_t g1 = g0 + 512;
            uint2 A  = *(const uint2*)(vh + g0);
            uint2 Bv = *(const uint2*)(vh + g1);
            Vhi[(4 * dpp + 0) * FST + kp] = __byte_perm(A.x, Bv.x, 0x5410);
            Vhi[(4 * dpp + 1) * FST + kp] = __byte_perm(A.x, Bv.x, 0x7632);
            Vhi[(4 * dpp + 2) * FST + kp] = __byte_perm(A.y, Bv.y, 0x5410);
            Vhi[(4 * dpp + 3) * FST + kp] = __byte_perm(A.y, Bv.y, 0x7632);
            uint2 C  = *(const uint2*)(vl + g0);
            uint2 Dv = *(const uint2*)(vl + g1);
            Vlo[(4 * dpp + 0) * FST + kp] = __byte_perm(C.x, Dv.x, 0x5410);
            Vlo[(4 * dpp + 1) * FST + kp] = __byte_perm(C.x, Dv.x, 0x7632);
            Vlo[(4 * dpp + 2) * FST + kp] = __byte_perm(C.y, Dv.y, 0x5410);
            Vlo[(4 * dpp + 3) * FST + kp] = __byte_perm(C.y, Dv.y, 0x7632);
        }
        CP_WAIT(0);
        __syncthreads();

        // ---- S = Q K^T (3-term)
        float S[8][4];
#pragma unroll
        for (int j = 0; j < 8; ++j)
#pragma unroll
            for (int r = 0; r < 4; ++r) S[j][r] = 0.0f;
#pragma unroll
        for (int j = 0; j < 8; ++j) {
            const int nr = j * 8 + g;
#pragma unroll
            for (int ks = 0; ks < 4; ++ks) {
                uint32_t bh0 = Khi[nr * FST + ks * 8 + t];
                uint32_t bh1 = Khi[nr * FST + ks * 8 + t + 4];
                uint32_t bl0 = Klo[nr * FST + ks * 8 + t];
                uint32_t bl1 = Klo[nr * FST + ks * 8 + t + 4];
                mma16816(S[j], qhf[ks][0], qhf[ks][1], qhf[ks][2], qhf[ks][3], bh0, bh1);
                mma16816(S[j], qlf[ks][0], qlf[ks][1], qlf[ks][2], qlf[ks][3], bh0, bh1);
                mma16816(S[j], qhf[ks][0], qhf[ks][1], qhf[ks][2], qhf[ks][3], bl0, bl1);
            }
        }

        // ---- Online softmax
        float mx0 = -1e30f, mx1 = -1e30f;
#pragma unroll
        for (int j = 0; j < 8; ++j) {
            mx0 = fmaxf(mx0, fmaxf(S[j][0], S[j][1]));
            mx1 = fmaxf(mx1, fmaxf(S[j][2], S[j][3]));
        }
        mx0 = fmaxf(mx0, __shfl_xor_sync(0xffffffffu, mx0, 1));
        mx0 = fmaxf(mx0, __shfl_xor_sync(0xffffffffu, mx0, 2));
        mx1 = fmaxf(mx1, __shfl_xor_sync(0xffffffffu, mx1, 1));
        mx1 = fmaxf(mx1, __shfl_xor_sync(0xffffffffu, mx1, 2));

        float mn0 = fmaxf(m0r, mx0);
        float mn1 = fmaxf(m1r, mx1);
        float cr0 = __expf(m0r - mn0);
        float cr1 = __expf(m1r - mn1);
        m0r = mn0; m1r = mn1;

        float sum0 = 0.0f, sum1 = 0.0f;
#pragma unroll
        for (int j = 0; j < 8; ++j) {
            S[j][0] = __expf(S[j][0] - mn0);
            S[j][1] = __expf(S[j][1] - mn0);
            S[j][2] = __expf(S[j][2] - mn1);
            S[j][3] = __expf(S[j][3] - mn1);
            sum0 += S[j][0] + S[j][1];
            sum1 += S[j][2] + S[j][3];
        }
        sum0 += __shfl_xor_sync(0xffffffffu, sum0, 1);
        sum0 += __shfl_xor_sync(0xffffffffu, sum0, 2);
        sum1 += __shfl_xor_sync(0xffffffffu, sum1, 1);
        sum1 += __shfl_xor_sync(0xffffffffu, sum1, 2);
        l0r = l0r * cr0 + sum0;
        l1r = l1r * cr1 + sum1;
#pragma unroll
        for (int j = 0; j < 8; ++j) {
            acc[j][0] *= cr0;
            acc[j][1] *= cr0;
            acc[j][2] *= cr1;
            acc[j][3] *= cr1;
        }

        // ---- O += P V (3-term, P from S fragments)
#pragma unroll
        for (int kb2 = 0; kb2 < 4; ++kb2) {
            uint32_t ph[4], pl[4];
            split2(S[2 * kb2][0],     S[2 * kb2][1],     ph[0], pl[0]);
            split2(S[2 * kb2][2],     S[2 * kb2][3],     ph[1], pl[1]);
            split2(S[2 * kb2 + 1][0], S[2 * kb2 + 1][1], ph[2], pl[2]);
            split2(S[2 * kb2 + 1][2], S[2 * kb2 + 1][3], ph[3], pl[3]);
#pragma unroll
            for (int j = 0; j < 8; ++j) {
                const int vr = j * 8 + g;
                uint32_t bh0 = Vhi[vr * FST + kb2 * 8 + t];
                uint32_t bh1 = Vhi[vr * FST + kb2 * 8 + t + 4];
                uint32_t bl0 = Vlo[vr * FST + kb2 * 8 + t];
                uint32_t bl1 = Vlo[vr * FST + kb2 * 8 + t + 4];
                mma16816(acc[j], ph[0], ph[1], ph[2], ph[3], bh0, bh1);
                mma16816(acc[j], pl[0], pl[1], pl[2], pl[3], bh0, bh1);
                mma16816(acc[j], ph[0], ph[1], ph[2], ph[3], bl0, bl1);
            }
        }
    }

    // ---- Normalize and store pre-split y
    float inv0 = 1.0f / l0r;
    float inv1 = 1.0f / l1r;
    int row0 = b * L_ + q0 + wid * 16 + g;
    size_t base0 = (size_t)row0 * 512 + h * 32;
    size_t base1 = base0 + 8 * 512;
#pragma unroll
    for (int j = 0; j < 8; ++j) {
        uint32_t h0, l0, h1, l1;
        split2(acc[j][0] * inv0, acc[j][1] * inv0, h0, l0);
        split2(acc[j][2] * inv1, acc[j][3] * inv1, h1, l1);
        yh[base0 + j * 4 + t] = h0;
        yl[base0 + j * 4 + t] = l0;
        yh[base1 + j * 4 + t] = h1;
        yl[base1 + j * 4 + t] = l1;
    }
}

// ---------------------------------------------------------------------------
// Host launcher
// ---------------------------------------------------------------------------
extern "C" void kernel_launch(void* const* d_in, const int* in_sizes, int n_in,
                              void* d_out, int out_size)
{
    const float* x  = (const float*)d_in[0];
    const float* Wq = (const float*)d_in[1];
    const float* Wk = (const float*)d_in[2];
    const float* Wv = (const float*)d_in[3];
    const float* Wo = (const float*)d_in[4];
    float* out = (float*)d_out;

    __nv_bfloat16 *xh, *xl, *wh, *wl, *qh, *ql, *kh, *kl, *vh, *vl;
    cudaGetSymbolAddress((void**)&xh, g_xh);
    cudaGetSymbolAddress((void**)&xl, g_xl);
    cudaGetSymbolAddress((void**)&wh, g_wh);
    cudaGetSymbolAddress((void**)&wl, g_wl);
    cudaGetSymbolAddress((void**)&qh, g_qh);
    cudaGetSymbolAddress((void**)&ql, g_ql);
    cudaGetSymbolAddress((void**)&kh, g_kh);
    cudaGetSymbolAddress((void**)&kl, g_kl);
    cudaGetSymbolAddress((void**)&vh, g_vh);
    cudaGetSymbolAddress((void**)&vl, g_vl);

    // 1. RoPE table, weight transpose+split, x split
    ropetab_kernel<<<(L_ * 32) / 256, 256>>>();
    splitw<<<dim3(D_ / 32, D_ / 32, 4), dim3(32, 8)>>>(Wq, Wk, Wv, Wo);
    split_f32<<<(M_ * D_ / 4) / 256, 256>>>(x, xh, xl);

    // 2. Fused QKV projection + RoPE + split epilogue
    cudaFuncSetAttribute(gemm_qkv,
                         cudaFuncAttributeMaxDynamicSharedMemorySize, GEMM2_SMEM);
    const float qscale = 1.0f / 32.0f;
    gemm_qkv<<<dim3(24, M_ / 128), 256, GEMM2_SMEM>>>(
        xh, xl, wh, wl,
        (uint32_t*)qh, (uint32_t*)ql, (uint32_t*)kh, (uint32_t*)kl,
        (uint32_t*)vh, (uint32_t*)vl, nullptr, qscale, 0);

    // 3. Flash attention on pre-split tensors; writes split y into xh/xl
    dim3 fgrid(L_ / 128, H_, B_);
    flash2<<<fgrid, 256>>>(
        (const uint32_t*)qh, (const uint32_t*)ql,
        (const uint32_t*)kh, (const uint32_t*)kl,
        (const uint32_t*)vh, (const uint32_t*)vl,
        (uint32_t*)xh, (uint32_t*)xl);

    // 4. Output projection (f32 out)
    gemm_qkv<<<dim3(8, M_ / 128), 256, GEMM2_SMEM>>>(
        xh, xl, wh + 3 * D_ * D_, wl + 3 * D_ * D_,
        nullptr, nullptr, nullptr, nullptr, nullptr, nullptr,
        out, 1.0f, 1);
}

// round 7
// speedup vs baseline: 1.2273x; 1.2273x over previous
#include <cuda_runtime.h>
#include <cuda_bf16.h>
#include <math.h>
#include <stdint.h>

// Problem constants
#define B_  2
#define L_  2048
#define D_  1024
#define H_  16
#define HD  64
#define M_  (B_ * L_)   // 4096

// ---------------------------------------------------------------------------
// Scratch (static device globals; no dynamic allocation allowed)
// ---------------------------------------------------------------------------
__device__ __nv_bfloat16 g_xh[M_ * D_];      // split of x; reused for y
__device__ __nv_bfloat16 g_xl[M_ * D_];
__device__ __nv_bfloat16 g_qh[M_ * D_];
__device__ __nv_bfloat16 g_ql[M_ * D_];
__device__ __nv_bfloat16 g_kh[M_ * D_];
__device__ __nv_bfloat16 g_kl[M_ * D_];
__device__ __nv_bfloat16 g_vh[M_ * D_];
__device__ __nv_bfloat16 g_vl[M_ * D_];
__device__ __nv_bfloat16 g_wh[4 * D_ * D_];  // transposed split weights
__device__ __nv_bfloat16 g_wl[4 * D_ * D_];
__device__ float2 g_rt[L_ * 32];             // (sin, cos) per (pos, pair)

// ---------------------------------------------------------------------------
// Helpers
// ---------------------------------------------------------------------------
__device__ __forceinline__ void mma16816(float* c,
                                         uint32_t a0, uint32_t a1,
                                         uint32_t a2, uint32_t a3,
                                         uint32_t b0, uint32_t b1)
{
    asm volatile(
        "mma.sync.aligned.m16n8k16.row.col.f32.bf16.bf16.f32 "
        "{%0,%1,%2,%3}, {%4,%5,%6,%7}, {%8,%9}, {%0,%1,%2,%3};"
        : "+f"(c[0]), "+f"(c[1]), "+f"(c[2]), "+f"(c[3])
        : "r"(a0), "r"(a1), "r"(a2), "r"(a3), "r"(b0), "r"(b1));
}

__device__ __forceinline__ void ldsm4(uint32_t& r0, uint32_t& r1,
                                      uint32_t& r2, uint32_t& r3, uint32_t a)
{
    asm volatile("ldmatrix.sync.aligned.m8n8.x4.shared.b16 {%0,%1,%2,%3}, [%4];"
                 : "=r"(r0), "=r"(r1), "=r"(r2), "=r"(r3) : "r"(a));
}

__device__ __forceinline__ void ldsm4t(uint32_t& r0, uint32_t& r1,
                                       uint32_t& r2, uint32_t& r3, uint32_t a)
{
    asm volatile("ldmatrix.sync.aligned.m8n8.x4.trans.shared.b16 {%0,%1,%2,%3}, [%4];"
                 : "=r"(r0), "=r"(r1), "=r"(r2), "=r"(r3) : "r"(a));
}

__device__ __forceinline__ void split2(float x0, float x1,
                                       uint32_t& hi, uint32_t& lo)
{
    __nv_bfloat162 hp = __floats2bfloat162_rn(x0, x1);
    float2 hf = __bfloat1622float2(hp);
    __nv_bfloat162 lp = __floats2bfloat162_rn(x0 - hf.x, x1 - hf.y);
    hi = *(uint32_t*)&hp;
    lo = *(uint32_t*)&lp;
}

__device__ __forceinline__ uint32_t smem_u32(const void* p) {
    uint32_t a;
    asm("{ .reg .u64 t; cvta.to.shared.u64 t, %1; cvt.u32.u64 %0, t; }"
        : "=r"(a) : "l"(p));
    return a;
}

__device__ __forceinline__ void cpa16(uint32_t dst, const void* src) {
    asm volatile("cp.async.cg.shared.global [%0], [%1], 16;"
                 :: "r"(dst), "l"(src));
}
#define CP_COMMIT  asm volatile("cp.async.commit_group;")
#define CP_WAIT(n) asm volatile("cp.async.wait_group %0;" :: "n"(n))

// ---------------------------------------------------------------------------
// RoPE table
// ---------------------------------------------------------------------------
__global__ __launch_bounds__(256) void ropetab_kernel()
{
    int idx = blockIdx.x * blockDim.x + threadIdx.x;   // < 65536
    int pos = idx >> 5;
    int i   = idx & 31;
    float freq = exp2f(-13.287712379549449f * (float)(2 * i) * (1.0f / 64.0f));
    float s, c;
    sincosf((float)pos * freq, &s, &c);
    g_rt[idx] = make_float2(s, c);
}

// ---------------------------------------------------------------------------
// split_f32
// ---------------------------------------------------------------------------
__global__ __launch_bounds__(256) void split_f32(
    const float* __restrict__ src,
    __nv_bfloat16* __restrict__ hi, __nv_bfloat16* __restrict__ lo)
{
    int i = blockIdx.x * blockDim.x + threadIdx.x;
    float4 v = ((const float4*)src)[i];
    uint32_t h0, l0, h1, l1;
    split2(v.x, v.y, h0, l0);
    split2(v.z, v.w, h1, l1);
    ((uint32_t*)hi)[2 * i]     = h0;
    ((uint32_t*)hi)[2 * i + 1] = h1;
    ((uint32_t*)lo)[2 * i]     = l0;
    ((uint32_t*)lo)[2 * i + 1] = l1;
}

// ---------------------------------------------------------------------------
// splitw: transpose + split weights
// ---------------------------------------------------------------------------
__global__ __launch_bounds__(256) void splitw(
    const float* __restrict__ W0, const float* __restrict__ W1,
    const float* __restrict__ W2, const float* __restrict__ W3)
{
    __shared__ float tile[32][33];
    const float* srcs[4] = {W0, W1, W2, W3};
    const float* src = srcs[blockIdx.z];

    int x = blockIdx.x * 32 + threadIdx.x;   // n
    int y = blockIdx.y * 32 + threadIdx.y;   // k
#pragma unroll
    for (int i = 0; i < 4; ++i)
        tile[threadIdx.y + i * 8][threadIdx.x] = src[(size_t)(y + i * 8) * D_ + x];
    __syncthreads();

    uint32_t* whu = (uint32_t*)g_wh;
    uint32_t* wlu = (uint32_t*)g_wl;
    int tid2 = threadIdx.y * 32 + threadIdx.x;
#pragma unroll
    for (int p = 0; p < 2; ++p) {
        int q = tid2 + p * 256;
        int nl = q >> 4;
        int kp = q & 15;
        uint32_t hi, lo;
        split2(tile[2 * kp][nl], tile[2 * kp + 1][nl], hi, lo);
        size_t o = ((size_t)(blockIdx.z * D_ + blockIdx.x * 32 + nl) * D_
                    + blockIdx.y * 32) / 2 + kp;
        whu[o] = hi;
        wlu[o] = lo;
    }
}

// ---------------------------------------------------------------------------
// gemm_qkv: C = alpha * A @ B^T, pre-split bf16, cp.async 2-stage, ldmatrix.
// mode 0: fused QKV + RoPE + split epilogue; mode 1: f32 output.
// ---------------------------------------------------------------------------
#define PST 20                       // smem row stride in u32 (80 bytes)
#define TILE_B (128 * PST * 4)       // 10240 bytes per operand tile
#define STAGE_B (4 * TILE_B)         // 40960
#define GEMM2_SMEM (2 * STAGE_B)     // 81920

__global__ __launch_bounds__(256, 2) void gemm_qkv(
    const __nv_bfloat16* __restrict__ Agh, const __nv_bfloat16* __restrict__ Agl,
    const __nv_bfloat16* __restrict__ Bgh, const __nv_bfloat16* __restrict__ Bgl,
    uint32_t* __restrict__ Qh, uint32_t* __restrict__ Ql,
    uint32_t* __restrict__ Kh, uint32_t* __restrict__ Kl,
    uint32_t* __restrict__ Vh, uint32_t* __restrict__ Vl,
    float* __restrict__ Of32, float alpha0, int mode)
{
    extern __shared__ char smp[];
    const uint32_t sb = smem_u32(smp);

    const int tid = threadIdx.x;
    const int wid = tid >> 5;
    const int lane = tid & 31;
    const int wm = wid & 1;
    const int wn = wid >> 1;
    const int g  = lane >> 2;
    const int t  = lane & 3;
    const int m0 = blockIdx.y * 128;
    const int nb = blockIdx.x;
    const int nrow0 = nb * 128;
    const int sel = nb >> 3;
    const float alpha = (sel == 0) ? alpha0 : 1.0f;
    const int n0 = (nb & 7) * 128;

    // ldmatrix lane offsets (bytes within a tile)
    const uint32_t aoff = (uint32_t)(((lane & 15) * PST + (lane >> 4) * 4) * 4);
    const uint32_t boff = (uint32_t)(((((lane >> 4) << 3) + (lane & 7)) * PST
                                      + ((lane >> 3) & 1) * 4) * 4);

    float acc[4][4][4];
#pragma unroll
    for (int i = 0; i < 4; ++i)
#pragma unroll
        for (int j = 0; j < 4; ++j)
#pragma unroll
            for (int r = 0; r < 4; ++r) acc[i][j][r] = 0.0f;

    const int ldrow = tid >> 2;
    const int ldcc  = tid & 3;

    auto issue = [&](int c, int s) {
        const int k0 = c * 32;
#pragma unroll
        for (int i = 0; i < 2; ++i) {
            int row = ldrow + i * 64;
            uint32_t so = (uint32_t)(s * STAGE_B + row * 80 + ldcc * 16);
            size_t ga = (size_t)(m0 + row) * D_ + k0 + ldcc * 8;
            size_t gb = (size_t)(nrow0 + row) * D_ + k0 + ldcc * 8;
            cpa16(sb + so,              Agh + ga);
            cpa16(sb + so + TILE_B,     Agl + ga);
            cpa16(sb + so + 2 * TILE_B, Bgh + gb);
            cpa16(sb + so + 3 * TILE_B, Bgl + gb);
        }
    };

    issue(0, 0);
    CP_COMMIT;

    for (int c = 0; c < D_ / 32; ++c) {
        const int s = c & 1;
        if (c + 1 < D_ / 32) {
            issue(c + 1, s ^ 1);
            CP_COMMIT;
            CP_WAIT(1);
        } else {
            CP_WAIT(0);
        }
        __syncthreads();

        const uint32_t Ab = sb + s * STAGE_B;
        const uint32_t Bb = Ab + 2 * TILE_B;

#pragma unroll
        for (int ks = 0; ks < 2; ++ks) {
            uint32_t bh[4][2], bl[4][2];
#pragma unroll
            for (int jp = 0; jp < 2; ++jp) {
                uint32_t ba = Bb + boff
                            + (uint32_t)(((wn * 32 + jp * 16) * PST + ks * 8) * 4);
                ldsm4(bh[2 * jp][0], bh[2 * jp][1],
                      bh[2 * jp + 1][0], bh[2 * jp + 1][1], ba);
                ldsm4(bl[2 * jp][0], bl[2 * jp][1],
                      bl[2 * jp + 1][0], bl[2 * jp + 1][1], ba + TILE_B);
            }
#pragma unroll
            for (int i = 0; i < 4; ++i) {
                uint32_t aa = Ab + aoff
                            + (uint32_t)(((wm * 64 + i * 16) * PST + ks * 8) * 4);
                uint32_t ah[4], al[4];
                ldsm4(ah[0], ah[1], ah[2], ah[3], aa);
                ldsm4(al[0], al[1], al[2], al[3], aa + TILE_B);
#pragma unroll
                for (int j = 0; j < 4; ++j) {
                    mma16816(acc[i][j], ah[0], ah[1], ah[2], ah[3], bh[j][0], bh[j][1]);
                    mma16816(acc[i][j], al[0], al[1], al[2], al[3], bh[j][0], bh[j][1]);
                    mma16816(acc[i][j], ah[0], ah[1], ah[2], ah[3], bl[j][0], bl[j][1]);
                }
            }
        }
        __syncthreads();
    }

    // ---- Epilogue
    uint32_t* Uh = (sel == 0) ? Qh : (sel == 1) ? Kh : Vh;
    uint32_t* Ul = (sel == 0) ? Ql : (sel == 1) ? Kl : Vl;

#pragma unroll
    for (int i = 0; i < 4; ++i) {
        int row = m0 + wm * 64 + i * 16 + g;
#pragma unroll
        for (int j = 0; j < 4; ++j) {
            int col = n0 + wn * 32 + j * 8 + t * 2;
            float2 o0 = make_float2(alpha * acc[i][j][0], alpha * acc[i][j][1]);
            float2 o1 = make_float2(alpha * acc[i][j][2], alpha * acc[i][j][3]);
            if (mode == 1) {
                *(float2*)(Of32 + (size_t)row * D_ + col)       = o0;
                *(float2*)(Of32 + (size_t)(row + 8) * D_ + col) = o1;
            } else {
                if (sel < 2) {   // RoPE for Q and K
                    int ii = (col >> 1) & 31;
                    float2 sc0 = g_rt[(row & (L_ - 1)) * 32 + ii];
                    float2 sc1 = g_rt[((row + 8) & (L_ - 1)) * 32 + ii];
                    o0 = make_float2(o0.x * sc0.y - o0.y * sc0.x,
                                     o0.y * sc0.y + o0.x * sc0.x);
                    o1 = make_float2(o1.x * sc1.y - o1.y * sc1.x,
                                     o1.y * sc1.y + o1.x * sc1.x);
                }
                uint32_t h0, l0, h1, l1;
                split2(o0.x, o0.y, h0, l0);
                split2(o1.x, o1.y, h1, l1);
                size_t u0 = ((size_t)row * D_ + col) >> 1;
                size_t u1 = ((size_t)(row + 8) * D_ + col) >> 1;
                Uh[u0] = h0; Ul[u0] = l0;
                Uh[u1] = h1; Ul[u1] = l1;
            }
        }
    }
}

// ---------------------------------------------------------------------------
// flash3: tensor-core flash attention, pre-split inputs, all-coalesced
// cp.async K/V (row layout), double-buffered tiles, ldmatrix fragments.
// ---------------------------------------------------------------------------
#define FROW_B 144                   // 36 u32 row stride
#define FARR_B (64 * FROW_B)         // 9216 bytes per array
#define FSTAGE_B (4 * FARR_B)        // 36864
#define FLASH_SMEM (2 * FSTAGE_B)    // 73728

__global__ __launch_bounds__(256, 2) void flash3(
    const uint32_t* __restrict__ qh, const uint32_t* __restrict__ ql,
    const uint32_t* __restrict__ kh, const uint32_t* __restrict__ kl,
    const uint32_t* __restrict__ vh, const uint32_t* __restrict__ vl,
    uint32_t* __restrict__ yh, uint32_t* __restrict__ yl)
{
    extern __shared__ char fsm[];
    const uint32_t sb = smem_u32(fsm);

    const int tid  = threadIdx.x;
    const int wid  = tid >> 5;
    const int lane = tid & 31;
    const int g = lane >> 2;
    const int t = lane & 3;
    const int q0 = blockIdx.x * 128;
    const int h  = blockIdx.y;
    const int b  = blockIdx.z;

    // ldmatrix lane offsets (bytes within an array)
    const uint32_t koff = (uint32_t)(((((lane >> 4) << 3) + (lane & 7)) * 36
                                      + ((lane >> 3) & 1) * 4) * 4);
    const uint32_t voff = (uint32_t)(((((lane >> 3) & 1) * 8 + (lane & 7)) * 36
                                      + (lane >> 4) * 4) * 4);

    // ---- Q fragments (direct loads from pre-split buffers)
    uint32_t qhf[4][4], qlf[4][4];
    {
        int r0 = b * L_ + q0 + wid * 16 + g;
        const uint32_t* p  = qh + (size_t)r0 * 512 + h * 32;
        const uint32_t* pl = ql + (size_t)r0 * 512 + h * 32;
#pragma unroll
        for (int ks = 0; ks < 4; ++ks) {
            qhf[ks][0] = p[ks * 8 + t];
            qhf[ks][1] = p[8 * 512 + ks * 8 + t];
            qhf[ks][2] = p[ks * 8 + t + 4];
            qhf[ks][3] = p[8 * 512 + ks * 8 + t + 4];
            qlf[ks][0] = pl[ks * 8 + t];
            qlf[ks][1] = pl[8 * 512 + ks * 8 + t];
            qlf[ks][2] = pl[ks * 8 + t + 4];
            qlf[ks][3] = pl[8 * 512 + ks * 8 + t + 4];
        }
    }

    const int ldrow = tid >> 2;     // 0..63
    const int ldch  = tid & 3;      // chunks ldch, ldch+4

    auto issue_kv = [&](int tile, int s) {
        size_t uoff = (size_t)(b * L_ + tile * 64 + ldrow) * 512 + h * 32;
        uint32_t so = sb + (uint32_t)(s * FSTAGE_B + ldrow * FROW_B);
#pragma unroll
        for (int c2 = 0; c2 < 2; ++c2) {
            int ch = ldch + c2 * 4;
            cpa16(so + ch * 16,                kh + uoff + ch * 4);
            cpa16(so + FARR_B + ch * 16,       kl + uoff + ch * 4);
            cpa16(so + 2 * FARR_B + ch * 16,   vh + uoff + ch * 4);
            cpa16(so + 3 * FARR_B + ch * 16,   vl + uoff + ch * 4);
        }
    };

    float acc[8][4];
#pragma unroll
    for (int j = 0; j < 8; ++j)
#pragma unroll
        for (int r = 0; r < 4; ++r) acc[j][r] = 0.0f;
    float m0r = -1e30f, m1r = -1e30f, l0r = 0.0f, l1r = 0.0f;

    issue_kv(0, 0);
    CP_COMMIT;

    for (int tile = 0; tile < L_ / 64; ++tile) {
        const int s = tile & 1;
        if (tile + 1 < L_ / 64) {
            issue_kv(tile + 1, s ^ 1);
            CP_COMMIT;
            CP_WAIT(1);
        } else {
            CP_WAIT(0);
        }
        __syncthreads();   // buffer s ready for all warps

        const uint32_t kb_ = sb + s * FSTAGE_B;        // Khi
        const uint32_t vb_ = kb_ + 2 * FARR_B;         // Vhi

        // ---- S = Q K^T (3-term) via ldmatrix
        float S[8][4];
#pragma unroll
        for (int j = 0; j < 8; ++j)
#pragma unroll
            for (int r = 0; r < 4; ++r) S[j][r] = 0.0f;
#pragma unroll
        for (int ks = 0; ks < 4; ++ks) {
#pragma unroll
            for (int jp = 0; jp < 4; ++jp) {
                uint32_t a = kb_ + koff + (uint32_t)(jp * 16 * FROW_B + ks * 32);
                uint32_t h0a, h1a, h0b, h1b, l0a, l1a, l0b, l1b;
                ldsm4(h0a, h1a, h0b, h1b, a);
                ldsm4(l0a, l1a, l0b, l1b, a + FARR_B);
                mma16816(S[2 * jp],     qhf[ks][0], qhf[ks][1], qhf[ks][2], qhf[ks][3], h0a, h1a);
                mma16816(S[2 * jp],     qlf[ks][0], qlf[ks][1], qlf[ks][2], qlf[ks][3], h0a, h1a);
                mma16816(S[2 * jp],     qhf[ks][0], qhf[ks][1], qhf[ks][2], qhf[ks][3], l0a, l1a);
                mma16816(S[2 * jp + 1], qhf[ks][0], qhf[ks][1], qhf[ks][2], qhf[ks][3], h0b, h1b);
                mma16816(S[2 * jp + 1], qlf[ks][0], qlf[ks][1], qlf[ks][2], qlf[ks][3], h0b, h1b);
                mma16816(S[2 * jp + 1], qhf[ks][0], qhf[ks][1], qhf[ks][2], qhf[ks][3], l0b, l1b);
            }
        }

        // ---- Online softmax
        float mx0 = -1e30f, mx1 = -1e30f;
#pragma unroll
        for (int j = 0; j < 8; ++j) {
            mx0 = fmaxf(mx0, fmaxf(S[j][0], S[j][1]));
            mx1 = fmaxf(mx1, fmaxf(S[j][2], S[j][3]));
        }
        mx0 = fmaxf(mx0, __shfl_xor_sync(0xffffffffu, mx0, 1));
        mx0 = fmaxf(mx0, __shfl_xor_sync(0xffffffffu, mx0, 2));
        mx1 = fmaxf(mx1, __shfl_xor_sync(0xffffffffu, mx1, 1));
        mx1 = fmaxf(mx1, __shfl_xor_sync(0xffffffffu, mx1, 2));

        float mn0 = fmaxf(m0r, mx0);
        float mn1 = fmaxf(m1r, mx1);
        float cr0 = __expf(m0r - mn0);
        float cr1 = __expf(m1r - mn1);
        m0r = mn0; m1r = mn1;

        float sum0 = 0.0f, sum1 = 0.0f;
#pragma unroll
        for (int j = 0; j < 8; ++j) {
            S[j][0] = __expf(S[j][0] - mn0);
            S[j][1] = __expf(S[j][1] - mn0);
            S[j][2] = __expf(S[j][2] - mn1);
            S[j][3] = __expf(S[j][3] - mn1);
            sum0 += S[j][0] + S[j][1];
            sum1 += S[j][2] + S[j][3];
        }
        sum0 += __shfl_xor_sync(0xffffffffu, sum0, 1);
        sum0 += __shfl_xor_sync(0xffffffffu, sum0, 2);
        sum1 += __shfl_xor_sync(0xffffffffu, sum1, 1);
        sum1 += __shfl_xor_sync(0xffffffffu, sum1, 2);
        l0r = l0r * cr0 + sum0;
        l1r = l1r * cr1 + sum1;
#pragma unroll
        for (int j = 0; j < 8; ++j) {
            acc[j][0] *= cr0;
            acc[j][1] *= cr0;
            acc[j][2] *= cr1;
            acc[j][3] *= cr1;
        }

        // ---- O += P V (3-term) via ldmatrix.trans on row-major V
#pragma unroll
        for (int kb2 = 0; kb2 < 4; ++kb2) {
            uint32_t ph[4], pl[4];
            split2(S[2 * kb2][0],     S[2 * kb2][1],     ph[0], pl[0]);
            split2(S[2 * kb2][2],     S[2 * kb2][3],     ph[1], pl[1]);
            split2(S[2 * kb2 + 1][0], S[2 * kb2 + 1][1], ph[2], pl[2]);
            split2(S[2 * kb2 + 1][2], S[2 * kb2 + 1][3], ph[3], pl[3]);
#pragma unroll
            for (int jp = 0; jp < 4; ++jp) {
                uint32_t a = vb_ + voff + (uint32_t)(kb2 * 16 * FROW_B + jp * 32);
                uint32_t h0a, h1a, h0b, h1b, l0a, l1a, l0b, l1b;
                ldsm4t(h0a, h1a, h0b, h1b, a);
                ldsm4t(l0a, l1a, l0b, l1b, a + FARR_B);
                mma16816(acc[2 * jp],     ph[0], ph[1], ph[2], ph[3], h0a, h1a);
                mma16816(acc[2 * jp],     pl[0], pl[1], pl[2], pl[3], h0a, h1a);
                mma16816(acc[2 * jp],     ph[0], ph[1], ph[2], ph[3], l0a, l1a);
                mma16816(acc[2 * jp + 1], ph[0], ph[1], ph[2], ph[3], h0b, h1b);
                mma16816(acc[2 * jp + 1], pl[0], pl[1], pl[2], pl[3], h0b, h1b);
                mma16816(acc[2 * jp + 1], ph[0], ph[1], ph[2], ph[3], l0b, l1b);
            }
        }
        __syncthreads();   // all warps done with buffer s before it is refilled
    }

    // ---- Normalize and store pre-split y
    float inv0 = 1.0f / l0r;
    float inv1 = 1.0f / l1r;
    int row0 = b * L_ + q0 + wid * 16 + g;
    size_t base0 = (size_t)row0 * 512 + h * 32;
    size_t base1 = base0 + 8 * 512;
#pragma unroll
    for (int j = 0; j < 8; ++j) {
        uint32_t h0, l0, h1, l1;
        split2(acc[j][0] * inv0, acc[j][1] * inv0, h0, l0);
        split2(acc[j][2] * inv1, acc[j][3] * inv1, h1, l1);
        yh[base0 + j * 4 + t] = h0;
        yl[base0 + j * 4 + t] = l0;
        yh[base1 + j * 4 + t] = h1;
        yl[base1 + j * 4 + t] = l1;
    }
}

// ---------------------------------------------------------------------------
// Host launcher
// ---------------------------------------------------------------------------
extern "C" void kernel_launch(void* const* d_in, const int* in_sizes, int n_in,
                              void* d_out, int out_size)
{
    const float* x  = (const float*)d_in[0];
    const float* Wq = (const float*)d_in[1];
    const float* Wk = (const float*)d_in[2];
    const float* Wv = (const float*)d_in[3];
    const float* Wo = (const float*)d_in[4];
    float* out = (float*)d_out;

    __nv_bfloat16 *xh, *xl, *wh, *wl, *qh, *ql, *kh, *kl, *vh, *vl;
    cudaGetSymbolAddress((void**)&xh, g_xh);
    cudaGetSymbolAddress((void**)&xl, g_xl);
    cudaGetSymbolAddress((void**)&wh, g_wh);
    cudaGetSymbolAddress((void**)&wl, g_wl);
    cudaGetSymbolAddress((void**)&qh, g_qh);
    cudaGetSymbolAddress((void**)&ql, g_ql);
    cudaGetSymbolAddress((void**)&kh, g_kh);
    cudaGetSymbolAddress((void**)&kl, g_kl);
    cudaGetSymbolAddress((void**)&vh, g_vh);
    cudaGetSymbolAddress((void**)&vl, g_vl);

    // 1. RoPE table, weight transpose+split, x split
    ropetab_kernel<<<(L_ * 32) / 256, 256>>>();
    splitw<<<dim3(D_ / 32, D_ / 32, 4), dim3(32, 8)>>>(Wq, Wk, Wv, Wo);
    split_f32<<<(M_ * D_ / 4) / 256, 256>>>(x, xh, xl);

    // 2. Fused QKV projection + RoPE + split epilogue
    cudaFuncSetAttribute(gemm_qkv,
                         cudaFuncAttributeMaxDynamicSharedMemorySize, GEMM2_SMEM);
    const float qscale = 1.0f / 32.0f;
    gemm_qkv<<<dim3(24, M_ / 128), 256, GEMM2_SMEM>>>(
        xh, xl, wh, wl,
        (uint32_t*)qh, (uint32_t*)ql, (uint32_t*)kh, (uint32_t*)kl,
        (uint32_t*)vh, (uint32_t*)vl, nullptr, qscale, 0);

    // 3. Flash attention; writes split y into xh/xl
    cudaFuncSetAttribute(flash3,
                         cudaFuncAttributeMaxDynamicSharedMemorySize, FLASH_SMEM);
    dim3 fgrid(L_ / 128, H_, B_);
    flash3<<<fgrid, 256, FLASH_SMEM>>>(
        (const uint32_t*)qh, (const uint32_t*)ql,
        (const uint32_t*)kh, (const uint32_t*)kl,
        (const uint32_t*)vh, (const uint32_t*)vl,
        (uint32_t*)xh, (uint32_t*)xl);

    // 4. Output projection (f32 out)
    gemm_qkv<<<dim3(8, M_ / 128), 256, GEMM2_SMEM>>>(
        xh, xl, wh + 3 * D_ * D_, wl + 3 * D_ * D_,
        nullptr, nullptr, nullptr, nullptr, nullptr, nullptr,
        out, 1.0f, 1);
}